// round 1
// baseline (speedup 1.0000x reference)
#include <cuda_runtime.h>
#include <cuda_bf16.h>

namespace {

constexpr int NH  = 32;    // query heads
constexpr int HS  = 128;   // head size
constexpr int KVH = 8;     // kv heads
constexpr int GRP = 4;     // NH / KVH
constexpr int B_  = 2;
constexpr int S_  = 2048;

constexpr int BR = 64;     // query rows per block
constexpr int BC = 64;     // keys per tile
constexpr int DK = 128;    // head dim

constexpr int QSTRIDE = DK + 4;   // 132 floats: conflict-free for frag loads
constexpr int KSTRIDE = DK + 4;   // 132
constexpr int VSTRIDE = DK + 8;   // 136
constexpr int SMEM_FLOATS = BR * QSTRIDE + BC * KSTRIDE + BC * VSTRIDE; // 25600
constexpr int SMEM_BYTES  = SMEM_FLOATS * 4;                            // 102400

__device__ __forceinline__ unsigned f2tf(float f) {
    unsigned r;
    asm("cvt.rna.tf32.f32 %0, %1;" : "=r"(r) : "f"(f));
    return r;
}

__device__ __forceinline__ void mma8(float c[4],
                                     unsigned a0, unsigned a1, unsigned a2, unsigned a3,
                                     unsigned b0, unsigned b1) {
    asm volatile(
        "mma.sync.aligned.m16n8k8.row.col.f32.tf32.tf32.f32 "
        "{%0,%1,%2,%3}, {%4,%5,%6,%7}, {%8,%9}, {%0,%1,%2,%3};"
        : "+f"(c[0]), "+f"(c[1]), "+f"(c[2]), "+f"(c[3])
        : "r"(a0), "r"(a1), "r"(a2), "r"(a3), "r"(b0), "r"(b1));
}

} // namespace

__global__ void __launch_bounds__(128)
gqa_flash_tf32(const float* __restrict__ q,
               const float* __restrict__ k,
               const float* __restrict__ v,
               float* __restrict__ out)
{
    extern __shared__ float sm[];
    float* sQ = sm;                       // [BR][QSTRIDE]
    float* sK = sQ + BR * QSTRIDE;        // [BC][KSTRIDE]
    float* sV = sK + BC * KSTRIDE;        // [BC][VSTRIDE]

    // Heavy (large qt) blocks first to reduce tail imbalance
    const int qt  = (int)gridDim.x - 1 - (int)blockIdx.x;
    const int h   = blockIdx.y;
    const int b   = blockIdx.z;
    const int kvh = h / GRP;

    const int tid  = threadIdx.x;
    const int warp = tid >> 5;
    const int lane = tid & 31;
    const int qq   = lane & 3;     // lane % 4
    const int rg   = lane >> 2;    // lane / 4
    const int q0   = qt * BR;
    const float scale = 0.0883883476483184405501f;  // 1/sqrt(128)

    // ---- Load Q tile, pre-scale, convert to tf32 bit pattern ----
    {
        const float* gQ = q + ((size_t)(b * S_ + q0) * NH + h) * HS;
        #pragma unroll 4
        for (int i = tid; i < BR * (DK / 4); i += 128) {
            int r  = i >> 5;       // DK/4 = 32 float4 per row
            int c4 = i & 31;
            float4 x = *(const float4*)(gQ + (size_t)r * (NH * HS) + c4 * 4);
            float* d = sQ + r * QSTRIDE + c4 * 4;
            d[0] = __uint_as_float(f2tf(x.x * scale));
            d[1] = __uint_as_float(f2tf(x.y * scale));
            d[2] = __uint_as_float(f2tf(x.z * scale));
            d[3] = __uint_as_float(f2tf(x.w * scale));
        }
    }

    float m0 = -1e30f, m1 = -1e30f;
    float l0 = 0.f,    l1 = 0.f;
    float o[16][4];
    #pragma unroll
    for (int i = 0; i < 16; ++i) { o[i][0] = o[i][1] = o[i][2] = o[i][3] = 0.f; }

    const int rowA = warp * 16 + rg;   // local row within Q tile (first half)

    for (int j = 0; j <= qt; ++j) {
        const int k0 = j * BC;
        __syncthreads();   // previous-iter readers done (also covers Q stores on iter 0)

        // ---- Load K, V tiles (coalesced), convert to tf32 bits ----
        {
            const float* gK = k + ((size_t)(b * S_ + k0) * KVH + kvh) * HS;
            const float* gV = v + ((size_t)(b * S_ + k0) * KVH + kvh) * HS;
            #pragma unroll 4
            for (int i = tid; i < BC * (DK / 4); i += 128) {
                int r  = i >> 5;
                int c4 = i & 31;
                float4 x = *(const float4*)(gK + (size_t)r * (KVH * HS) + c4 * 4);
                float* dk = sK + r * KSTRIDE + c4 * 4;
                dk[0] = __uint_as_float(f2tf(x.x));
                dk[1] = __uint_as_float(f2tf(x.y));
                dk[2] = __uint_as_float(f2tf(x.z));
                dk[3] = __uint_as_float(f2tf(x.w));
                float4 y = *(const float4*)(gV + (size_t)r * (KVH * HS) + c4 * 4);
                float* dv = sV + r * VSTRIDE + c4 * 4;
                dv[0] = __uint_as_float(f2tf(y.x));
                dv[1] = __uint_as_float(f2tf(y.y));
                dv[2] = __uint_as_float(f2tf(y.z));
                dv[3] = __uint_as_float(f2tf(y.w));
            }
        }
        __syncthreads();

        // ---- S = Q @ K^T (tf32 mma) : per warp 16 x 64 ----
        float s[8][4];
        #pragma unroll
        for (int i = 0; i < 8; ++i) { s[i][0] = s[i][1] = s[i][2] = s[i][3] = 0.f; }

        #pragma unroll
        for (int kt = 0; kt < 16; ++kt) {
            const float* qa = sQ + rowA * QSTRIDE + kt * 8 + qq;
            unsigned a0 = __float_as_uint(qa[0]);
            unsigned a1 = __float_as_uint(qa[8 * QSTRIDE]);
            unsigned a2 = __float_as_uint(qa[4]);
            unsigned a3 = __float_as_uint(qa[8 * QSTRIDE + 4]);
            #pragma unroll
            for (int nt = 0; nt < 8; ++nt) {
                const float* kb = sK + (nt * 8 + rg) * KSTRIDE + kt * 8 + qq;
                unsigned b0 = __float_as_uint(kb[0]);
                unsigned b1 = __float_as_uint(kb[4]);
                mma8(s[nt], a0, a1, a2, a3, b0, b1);
            }
        }

        // ---- Causal mask (diagonal tile only; q0 == k0 there) ----
        if (j == qt) {
            #pragma unroll
            for (int nt = 0; nt < 8; ++nt) {
                int c = nt * 8 + 2 * qq;
                if (c     > rowA)     s[nt][0] = -1e30f;
                if (c + 1 > rowA)     s[nt][1] = -1e30f;
                if (c     > rowA + 8) s[nt][2] = -1e30f;
                if (c + 1 > rowA + 8) s[nt][3] = -1e30f;
            }
        }

        // ---- Online softmax update ----
        float mx0 = -1e30f, mx1 = -1e30f;
        #pragma unroll
        for (int nt = 0; nt < 8; ++nt) {
            mx0 = fmaxf(mx0, fmaxf(s[nt][0], s[nt][1]));
            mx1 = fmaxf(mx1, fmaxf(s[nt][2], s[nt][3]));
        }
        mx0 = fmaxf(mx0, __shfl_xor_sync(0xffffffffu, mx0, 1));
        mx0 = fmaxf(mx0, __shfl_xor_sync(0xffffffffu, mx0, 2));
        mx1 = fmaxf(mx1, __shfl_xor_sync(0xffffffffu, mx1, 1));
        mx1 = fmaxf(mx1, __shfl_xor_sync(0xffffffffu, mx1, 2));

        float mn0 = fmaxf(m0, mx0), mn1 = fmaxf(m1, mx1);
        float al0 = __expf(m0 - mn0), al1 = __expf(m1 - mn1);
        m0 = mn0; m1 = mn1;

        float su0 = 0.f, su1 = 0.f;
        #pragma unroll
        for (int nt = 0; nt < 8; ++nt) {
            s[nt][0] = __expf(s[nt][0] - mn0);
            s[nt][1] = __expf(s[nt][1] - mn0);
            su0 += s[nt][0] + s[nt][1];
            s[nt][2] = __expf(s[nt][2] - mn1);
            s[nt][3] = __expf(s[nt][3] - mn1);
            su1 += s[nt][2] + s[nt][3];
        }
        su0 += __shfl_xor_sync(0xffffffffu, su0, 1);
        su0 += __shfl_xor_sync(0xffffffffu, su0, 2);
        su1 += __shfl_xor_sync(0xffffffffu, su1, 1);
        su1 += __shfl_xor_sync(0xffffffffu, su1, 2);
        l0 = l0 * al0 + su0;
        l1 = l1 * al1 + su1;

        #pragma unroll
        for (int nt = 0; nt < 16; ++nt) {
            o[nt][0] *= al0; o[nt][1] *= al0;
            o[nt][2] *= al1; o[nt][3] *= al1;
        }

        // ---- O += P @ V ----
        // Re-layout P from C-fragment (cols 2*qq,2*qq+1) to A-fragment (cols qq, qq+4)
        // via quad shuffles, then tf32 mma against row-major V.
        const int srcA = (lane & ~3) | (qq >> 1);
        #pragma unroll
        for (int kk = 0; kk < 8; ++kk) {
            float e0 = __shfl_sync(0xffffffffu, s[kk][0], srcA);
            float e1 = __shfl_sync(0xffffffffu, s[kk][1], srcA);
            float e2 = __shfl_sync(0xffffffffu, s[kk][2], srcA);
            float e3 = __shfl_sync(0xffffffffu, s[kk][3], srcA);
            float g0 = __shfl_sync(0xffffffffu, s[kk][0], srcA + 2);
            float g1 = __shfl_sync(0xffffffffu, s[kk][1], srcA + 2);
            float g2 = __shfl_sync(0xffffffffu, s[kk][2], srcA + 2);
            float g3 = __shfl_sync(0xffffffffu, s[kk][3], srcA + 2);
            bool od = (qq & 1);
            unsigned A0 = f2tf(od ? e1 : e0);   // P[rowA   ][kk*8+qq  ]
            unsigned A1 = f2tf(od ? e3 : e2);   // P[rowA+8 ][kk*8+qq  ]
            unsigned A2 = f2tf(od ? g1 : g0);   // P[rowA   ][kk*8+qq+4]
            unsigned A3 = f2tf(od ? g3 : g2);   // P[rowA+8 ][kk*8+qq+4]
            #pragma unroll
            for (int nt = 0; nt < 16; ++nt) {
                const float* vb = sV + (kk * 8 + qq) * VSTRIDE + nt * 8 + rg;
                unsigned b0 = __float_as_uint(vb[0]);
                unsigned b1 = __float_as_uint(vb[4 * VSTRIDE]);
                mma8(o[nt], A0, A1, A2, A3, b0, b1);
            }
        }
    }

    // ---- Epilogue: normalize and store ----
    const float inv0 = 1.f / l0;
    const float inv1 = 1.f / l1;
    float* gO0 = out + ((size_t)(b * S_ + q0 + rowA) * NH + h) * HS;
    float* gO1 = gO0 + (size_t)8 * NH * HS;
    #pragma unroll
    for (int nt = 0; nt < 16; ++nt) {
        int c = nt * 8 + 2 * qq;
        float2 v0 = make_float2(o[nt][0] * inv0, o[nt][1] * inv0);
        float2 v1 = make_float2(o[nt][2] * inv1, o[nt][3] * inv1);
        *(float2*)(gO0 + c) = v0;
        *(float2*)(gO1 + c) = v1;
    }
}

extern "C" void kernel_launch(void* const* d_in, const int* in_sizes, int n_in,
                              void* d_out, int out_size)
{
    (void)in_sizes; (void)n_in; (void)out_size;
    const float* q = (const float*)d_in[0];
    const float* k = (const float*)d_in[1];
    const float* v = (const float*)d_in[2];
    float* o = (float*)d_out;

    cudaFuncSetAttribute(gqa_flash_tf32,
                         cudaFuncAttributeMaxDynamicSharedMemorySize, SMEM_BYTES);

    dim3 grid(S_ / BR, NH, B_);   // (32, 32, 2)
    gqa_flash_tf32<<<grid, 128, SMEM_BYTES>>>(q, k, v, o);
}